// round 14
// baseline (speedup 1.0000x reference)
#include <cuda_runtime.h>

#define NB 4
#define NK 128
#define NG 128

// ---- output layout (float32, tuple flattened & concatenated) ----
#define OFF_ROIS    0
#define OFF_OBJ     2048
#define OFF_DELTAS  526336
#define OFF_RANKS   528384
#define OFF_SPATIAL 528896

// Per-image sync state, one 128B line each (zero-initialized; the 16th
// done-arriver of each image resets it for the next launch).
struct __align__(128) ImgSync {
    unsigned long long arrive[2];   // 128 arrival bits
    unsigned long long pos[2];      // 128 positive bits
    int done;
    int pad[23];
};
__device__ ImgSync g_sync[NB];

// grid = 64, block = 256. Block g owns 8 consecutive source proposals
// s = 8g..8g+7 of image b = g>>4 (16 blocks per image). Warp w computes
// proposal (8g+w)'s 128 IoUs (4 GTs per lane) and its lane 0 precomputes
// the scalar outputs. t==0 publishes all 8 bits with ONE RED per word,
// polls the image's arrive words, then every warp's lane 0 derives its
// dest; finally all 256 threads scatter the 8 payloads + spatial maps.
__global__ void __launch_bounds__(256) fused_kernel(
    const float* __restrict__ proposals,
    const float* __restrict__ obj_feat,
    const float* __restrict__ gt_boxes,
    const int*   __restrict__ gt_ranks,
    float*       __restrict__ out)
{
    const int g    = blockIdx.x;
    const int b    = g >> 4;
    const int t    = threadIdx.x;
    const int w    = t >> 5;          // warp = which of the 8 proposals
    const int lane = t & 31;
    const int sbase = g * 8;          // first source index of this block
    const int s     = sbase + w;      // this warp's source proposal
    const int p     = s & 127;

    // ---- payload loads first: 8 independent streams, overlap everything ----
    float4 pay[8];
    #pragma unroll
    for (int ww = 0; ww < 8; ww++)
        pay[ww] = ((const float4*)obj_feat)[(size_t)(sbase + ww) * 256 + t];

    __shared__ int  s_pos[8];
    __shared__ unsigned long long s_pw[2];
    __shared__ int  s_dest[8];
    __shared__ int4 s_box[8];

    // ---- per-warp argmax: lane handles GTs {lane, lane+32, lane+64, lane+96} ----
    const float4 pr = ((const float4*)proposals)[s];     // warp-broadcast
    const float ap = (pr.z - pr.x) * (pr.w - pr.y);
    float bi = -1.0f, bu = 1.0f;
    int   bj = lane;
    #pragma unroll
    for (int k = 0; k < 4; k++) {
        const int j = lane + k * 32;
        const float4 gt = ((const float4*)gt_boxes)[(b << 7) + j];
        const float dy = fminf(pr.z, gt.z) - fmaxf(pr.x, gt.x);
        const float dx = fminf(pr.w, gt.w) - fmaxf(pr.y, gt.y);
        const float inter = fmaxf(dx, 0.0f) * fmaxf(dy, 0.0f);
        const float u = ap + (gt.z - gt.x) * (gt.w - gt.y) - inter;
        // ascending j within lane: strict > keeps first max
        if (inter * bu > bi * u) { bi = inter; bu = u; bj = j; }
    }
    // warp reduce with explicit index tie-break (GT order across lanes is
    // strided, so equal values must resolve to the LOWEST GT index).
    #pragma unroll
    for (int off = 16; off; off >>= 1) {
        const float oi = __shfl_down_sync(0xFFFFFFFFu, bi, off);
        const float ou = __shfl_down_sync(0xFFFFFFFFu, bu, off);
        const int   oj = __shfl_down_sync(0xFFFFFFFFu, bj, off);
        const float pa = oi * bu, pb = bi * ou;
        if (pa > pb || (pa == pb && oj < bj)) { bi = oi; bu = ou; bj = oj; }
    }

    // ---- lane 0 of each warp: exact IoU, pos, dest-independent precompute ----
    int   pos = 0;
    float4 dl = make_float4(0.f, 0.f, 0.f, 0.f);
    float rk = 0.0f;
    int4  box = make_int4(0, 0, 0, 0);
    if (lane == 0) {
        const float4 gb = ((const float4*)gt_boxes)[(b << 7) + bj];
        // exact IoU for the winner (bit-matches reference threshold test)
        const float iy1 = fmaxf(pr.x, gb.x);
        const float ix1 = fmaxf(pr.y, gb.y);
        const float iy2 = fminf(pr.z, gb.z);
        const float ix2 = fminf(pr.w, gb.w);
        const float inter = fmaxf(ix2 - ix1, 0.0f) * fmaxf(iy2 - iy1, 0.0f);
        const float ag = (gb.z - gb.x) * (gb.w - gb.y);
        const float iou = inter / (ap + ag - inter);
        pos = (iou >= 0.5f) ? 1 : 0;
        s_pos[w] = pos;

        float gy1 = gb.x, gx1 = gb.y, gy2 = gb.z, gx2 = gb.w;
        if (pos) {
            const float h  = pr.z - pr.x, wd = pr.w - pr.y;
            const float cy = pr.x + 0.5f * h, cx = pr.y + 0.5f * wd;
            const float gh = gy2 - gy1, gw = gx2 - gx1;
            const float gcy = gy1 + 0.5f * gh, gcx = gx1 + 0.5f * gw;
            dl.x = ((gcy - cy) / h)  / 0.1f;
            dl.y = ((gcx - cx) / wd) / 0.1f;
            dl.z = logf(gh / h)  / 0.2f;
            dl.w = logf(gw / wd) / 0.2f;
            rk = (float)gt_ranks[b * NG + bj];
        } else {
            gy1 = gx1 = gy2 = gx2 = 0.0f;    // roi_gt = 0 for negatives
        }
        // integer spatial box (window transform + denorm + round-half-even)
        const float win0 = 128.0f / 1023.0f;
        const float win2 = 895.0f / 1023.0f;
        const float wsc  = win2 - win0;
        int by1 = (int)rintf(((gy1 - win0) / wsc) * 479.0f);
        int bx1 = (int)rintf(gx1 * 639.0f);
        int by2 = (int)rintf(((gy2 - win0) / wsc) * 479.0f + 1.0f);
        int bx2 = (int)rintf(gx2 * 639.0f + 1.0f);
        if (!((by2 - by1) * (bx2 - bx1) > 0)) { by1 = bx1 = by2 = bx2 = 0; }
        box = make_int4(by1, bx1, by2, bx2);
    }
    __syncthreads();

    // ---- t==0: single publish for all 8 proposals, then poll ----
    if (t == 0) {
        ImgSync* S = &g_sync[b];
        const int base = (g & 15) * 8;        // bit base within image, 8-aligned
        const int w64  = base >> 6;
        const int sh   = base & 63;
        unsigned long long pbits = 0;
        #pragma unroll
        for (int ww = 0; ww < 8; ww++)
            pbits |= ((unsigned long long)s_pos[ww]) << (sh + ww);
        const unsigned long long abits = 0xFFULL << sh;

        if (pbits)
            asm volatile("red.relaxed.gpu.global.or.b64 [%0], %1;"
                         :: "l"(&S->pos[w64]), "l"(pbits) : "memory");
        asm volatile("red.release.gpu.global.or.b64 [%0], %1;"
                     :: "l"(&S->arrive[w64]), "l"(abits) : "memory");

        // wait for all 128 arrivals of this image (16 publishers only)
        unsigned long long a0, a1;
        int spins = 0;
        for (;;) {
            asm volatile("ld.acquire.gpu.global.b64 %0, [%1];"
                         : "=l"(a0) : "l"(&S->arrive[0]) : "memory");
            asm volatile("ld.acquire.gpu.global.b64 %0, [%1];"
                         : "=l"(a1) : "l"(&S->arrive[1]) : "memory");
            if ((a0 & a1) == ~0ULL) break;
            if (++spins > 256) __nanosleep(32);
        }
        unsigned long long p0, p1;
        asm volatile("ld.relaxed.gpu.global.b64 %0, [%1];"
                     : "=l"(p0) : "l"(&S->pos[0]) : "memory");
        asm volatile("ld.relaxed.gpu.global.b64 %0, [%1];"
                     : "=l"(p1) : "l"(&S->pos[1]) : "memory");
        s_pw[0] = p0;
        s_pw[1] = p1;

        // done counter; the 16th arriver resets this image's sync words.
        // (atom.release orders the pos reads above before the add; every
        //  block adds only after it has read pos, so reset is safe.)
        int old, one = 1;
        asm volatile("atom.release.gpu.global.add.s32 %0, [%1], %2;"
                     : "=r"(old) : "l"(&S->done), "r"(one) : "memory");
        if (old == 15) {
            const unsigned long long z = 0ULL;
            asm volatile("st.relaxed.gpu.global.b64 [%0], %1;" :: "l"(&S->arrive[0]), "l"(z) : "memory");
            asm volatile("st.relaxed.gpu.global.b64 [%0], %1;" :: "l"(&S->arrive[1]), "l"(z) : "memory");
            asm volatile("st.relaxed.gpu.global.b64 [%0], %1;" :: "l"(&S->pos[0]),    "l"(z) : "memory");
            asm volatile("st.relaxed.gpu.global.b64 [%0], %1;" :: "l"(&S->pos[1]),    "l"(z) : "memory");
            int zi = 0;
            asm volatile("st.relaxed.gpu.global.b32 [%0], %1;" :: "l"(&S->done), "r"(zi) : "memory");
        }
    }
    __syncthreads();

    // ---- each warp's lane 0: derive dest, write scalar outputs ----
    if (lane == 0) {
        const unsigned long long p0 = s_pw[0], p1 = s_pw[1];
        const int npos = __popcll(p0) + __popcll(p1);
        const unsigned long long bit = 1ULL << (p & 63);
        const unsigned long long myw = (p < 64) ? p0 : p1;
        int below = __popcll(myw & (bit - 1));
        if (p >= 64) below += __popcll(p0);
        const int dest = pos ? below : (npos + (p - below));
        const int dbo  = (b << 7) + dest;

        ((float4*)(out + OFF_ROIS))[dbo]   = pr;
        ((float4*)(out + OFF_DELTAS))[dbo] = dl;
        out[OFF_RANKS + dbo] = rk;

        s_dest[w] = dest;
        s_box[w]  = box;
    }
    __syncthreads();

    // ---- scatter: 8 payloads + 8 analytic spatial maps ----
    const int row  = t >> 3;
    const int col0 = (t & 7) * 4;
    const int r1   = 20 * (row - 4) + 9;
    const bool inband = (row >= 4 && row < 28);

    #pragma unroll
    for (int ww = 0; ww < 8; ww++) {
        const int dbo = (b << 7) + s_dest[ww];
        ((float4*)(out + OFF_OBJ))[(size_t)dbo * 256 + t] = pay[ww];

        const int4 bx = s_box[ww];
        float4 v = make_float4(0.f, 0.f, 0.f, 0.f);
        if (inband) {
            const float fy = (float)((bx.x < r1)     && (r1     < bx.z))
                           + (float)((bx.x < r1 + 1) && (r1 + 1 < bx.z));
            const float sc = 0.25f * fy;
            float* vv = &v.x;
            #pragma unroll
            for (int k = 0; k < 4; k++) {
                const int c1 = 20 * (col0 + k) + 9;
                const float fx = (float)((bx.y < c1)     && (c1     < bx.w))
                               + (float)((bx.y < c1 + 1) && (c1 + 1 < bx.w));
                vv[k] = sc * fx;
            }
        }
        ((float4*)(out + OFF_SPATIAL))[(size_t)dbo * 256 + t] = v;
    }
}

extern "C" void kernel_launch(void* const* d_in, const int* in_sizes, int n_in,
                              void* d_out, int out_size)
{
    const float* proposals = (const float*)d_in[0];
    const float* obj_feat  = (const float*)d_in[1];
    const float* gt_boxes  = (const float*)d_in[2];
    const int*   gt_ranks  = (const int*)  d_in[3];
    float* out = (float*)d_out;

    fused_kernel<<<64, 256>>>(proposals, obj_feat, gt_boxes, gt_ranks, out);
}